// round 5
// baseline (speedup 1.0000x reference)
#include <cuda_runtime.h>
#include <math.h>

#define BATCH 2048
#define NC    9605
#define NL    8
#define MAXWL 512
#define NTHR  256
#define WLB   32

__device__ int           g_wl_count;   // 0-init; reset by row tail each launch
__device__ int           g_wl_idx[MAXWL];
__device__ unsigned char g_wl_mask[MAXWL];
__device__ float         g_row_val[BATCH];
__device__ int           g_done;       // 0-init; reset by row tail each launch

__device__ __forceinline__ float sigmoidf_(float v) {
    return 1.0f / (1.0f + expf(-v));   // v = -1e30 -> 0 (correct)
}
__device__ __forceinline__ unsigned f2k(unsigned u) {          // monotone float->uint
    return (u & 0x80000000u) ? ~u : (u | 0x80000000u);
}
__device__ __forceinline__ float k2f(unsigned k) {
    return (k & 0x80000000u) ? __uint_as_float(k ^ 0x80000000u)
                             : __uint_as_float(~k);
}

// ---------------------------------------------------------------------------
// Kernel 1: fused dtype-sniff + whitelist compaction. Each block redundantly
// scans the wl buffer for dtype flags (hits L2), then builds its column stripe.
// Reads only the first NL*NC bytes -> in-bounds under any dtype hypothesis.
// ---------------------------------------------------------------------------
__global__ void __launch_bounds__(NTHR) build_wl_kernel(const void* __restrict__ wlraw) {
    __shared__ int fl[4];          // badint, anyint1(unused), badf, anyf1
    const int tid = threadIdx.x;
    if (tid < 4) fl[tid] = 0;
    __syncthreads();

    const int NQ = (NL * NC) / 4;
    const int*   ip = (const int*)wlraw;
    const float* fp = (const float*)wlraw;
    for (int i = tid; i < NQ; i += NTHR) {
        int v = ip[i];
        float f = fp[i];
        if (v != 0 && v != 1)          fl[0] = 1;
        if (!(f == 0.0f || f == 1.0f)) fl[2] = 1;
        if (f == 1.0f)                 fl[3] = 1;
    }
    __syncthreads();
    const int mode = (!fl[2] && fl[3]) ? 2 : (!fl[0] ? 1 : 0);  // 2=f32,1=i32,0=u8
    const unsigned char* up = (const unsigned char*)wlraw;

    for (int c = blockIdx.x * NTHR + tid; c < NC; c += WLB * NTHR) {
        unsigned m = 0;
#pragma unroll
        for (int l = 0; l < NL; ++l) {
            bool on;
            if      (mode == 2) on = (fp[l * NC + c] != 0.0f);
            else if (mode == 1) on = (ip[l * NC + c] != 0);
            else                on = (up[l * NC + c] != 0);
            if (on) m |= (1u << l);
        }
        if (m) {
            int p = atomicAdd(&g_wl_count, 1);
            g_wl_idx[p]  = c;
            g_wl_mask[p] = (unsigned char)m;
        }
    }
}

// ---------------------------------------------------------------------------
// pick_bin: given a BP*NTHR-bin histogram (thread t owns bins [t*BP, t*BP+BP)),
// find the bin containing the `want`-th largest element and its in-bin rank.
// Hierarchical suffix scan: warp shfl + 8 warp totals. 2 barriers.
// ---------------------------------------------------------------------------
template <int BP>
__device__ __forceinline__ void pick_bin(const unsigned* __restrict__ hist,
                                         unsigned* __restrict__ wsum,
                                         unsigned* __restrict__ sb,
                                         unsigned* __restrict__ sw,
                                         unsigned want, int tid) {
    unsigned v[BP];
    unsigned tot = 0;
#pragma unroll
    for (int i = 0; i < BP; ++i) { v[i] = hist[tid * BP + i]; tot += v[i]; }
    unsigned incl = tot;                      // inclusive suffix within warp
#pragma unroll
    for (int d = 1; d < 32; d <<= 1) {
        unsigned n = __shfl_down_sync(0xffffffffu, incl, d);
        if ((tid & 31) + d < 32) incl += n;
    }
    if ((tid & 31) == 0) wsum[tid >> 5] = incl;
    __syncthreads();
    unsigned above = incl - tot;              // strictly-higher lanes, same warp
#pragma unroll
    for (int w = 0; w < NTHR / 32; ++w)
        if (w > (tid >> 5)) above += wsum[w];
    unsigned suf = above;                     // # elements in bins > current j
#pragma unroll
    for (int j = BP - 1; j >= 0; --j) {
        unsigned nsuf = suf + v[j];
        if (suf < want && want <= nsuf) { *sb = (unsigned)(tid * BP + j); *sw = want - suf; }
        suf = nsuf;
    }
    __syncthreads();
}

// ---------------------------------------------------------------------------
// Kernel 2: one block per row. Level-0 (11-bit) histogram fused into the DRAM
// stream; levels 1-2 are near-free predicate scans (almost no matches). Then
// whitelist maxes / pos bits / union max, epilogue, and last-block mean.
// ---------------------------------------------------------------------------
__global__ void __launch_bounds__(NTHR)
row_kernel(const float* __restrict__ x, const float* __restrict__ y,
           float* __restrict__ out) {
    __shared__ unsigned s_keys[NC];
    __shared__ unsigned s_hist[2048];
    __shared__ unsigned s_wsum[NTHR / 32];
    __shared__ unsigned s_bin, s_want;
    __shared__ unsigned s_lmaxk[NTHR / 32][NL];
    __shared__ unsigned s_unk[NTHR / 32];
    __shared__ unsigned s_pb[NTHR / 32];
    __shared__ int      s_last;

    const int b   = blockIdx.x;
    const int tid = threadIdx.x;
    const float* xr = x + (size_t)b * NC;
    const float* yr = y + (size_t)b * NC;

#pragma unroll
    for (int i = 0; i < 8; ++i) s_hist[tid * 8 + i] = 0;
    __syncthreads();

    // ---- phase A: DRAM stream + key store + fused level-0 histogram ----
    for (int base = 0; base < NC; base += NTHR) {
        const int c = base + tid;
        const bool m = (c < NC);
        unsigned key = 0, bin = 0;
        if (m) {
            key = f2k(__float_as_uint(__ldg(xr + c)));
            s_keys[c] = key;
            bin = key >> 21;
        }
        unsigned act = __ballot_sync(0xffffffffu, m);
        if (m) {
            unsigned grp = __match_any_sync(act, bin);
            if ((int)(tid & 31) == (__ffs(grp) - 1))
                atomicAdd(&s_hist[bin], (unsigned)__popc(grp));
        }
    }
    __syncthreads();

    // ---- level 0: pick 11-bit prefix ----
    unsigned want = 11;
    pick_bin<8>(s_hist, s_wsum, &s_bin, &s_want, want, tid);
    unsigned prefix = s_bin;
    want = s_want;
    __syncthreads();

    // ---- level 1: bits [20:10]; only ~want elements match prefix ----
#pragma unroll
    for (int i = 0; i < 8; ++i) s_hist[tid * 8 + i] = 0;
    __syncthreads();
    for (int base = 0; base < NC; base += NTHR) {
        const int c = base + tid;
        bool m = (c < NC);
        unsigned key = 0, bin = 0;
        if (m) {
            key = s_keys[c];
            m = ((key >> 21) == prefix);
            bin = (key >> 10) & 0x7FFu;
        }
        unsigned act = __ballot_sync(0xffffffffu, m);
        if (act == 0) continue;
        if (m) {
            unsigned grp = __match_any_sync(act, bin);
            if ((int)(tid & 31) == (__ffs(grp) - 1))
                atomicAdd(&s_hist[bin], (unsigned)__popc(grp));
        }
    }
    __syncthreads();
    pick_bin<8>(s_hist, s_wsum, &s_bin, &s_want, want, tid);
    prefix = (prefix << 11) | s_bin;
    want = s_want;
    __syncthreads();

    // ---- level 2: bits [9:0] ----
#pragma unroll
    for (int i = 0; i < 4; ++i) s_hist[tid * 4 + i] = 0;
    __syncthreads();
    for (int base = 0; base < NC; base += NTHR) {
        const int c = base + tid;
        bool m = (c < NC);
        unsigned key = 0, bin = 0;
        if (m) {
            key = s_keys[c];
            m = ((key >> 10) == prefix);
            bin = key & 0x3FFu;
        }
        unsigned act = __ballot_sync(0xffffffffu, m);
        if (act == 0) continue;
        if (m) {
            unsigned grp = __match_any_sync(act, bin);
            if ((int)(tid & 31) == (__ffs(grp) - 1))
                atomicAdd(&s_hist[bin], (unsigned)__popc(grp));
        }
    }
    __syncthreads();
    pick_bin<4>(s_hist, s_wsum, &s_bin, &s_want, want, tid);
    const unsigned key11 = (prefix << 10) | s_bin;   // exact 11th-largest key
    __syncthreads();

    // ---- whitelist gather (x keys from smem, y sparse from DRAM) ----
    const unsigned KNEG = f2k(__float_as_uint(-1e30f));
    const int nwl = g_wl_count;
    unsigned lmaxk[NL];
#pragma unroll
    for (int l = 0; l < NL; ++l) lmaxk[l] = KNEG;
    unsigned unk = KNEG, pos = 0;

    for (int e = tid; e < nwl; e += NTHR) {
        const int      c  = g_wl_idx[e];
        const unsigned m  = g_wl_mask[e];
        const unsigned kv = s_keys[c];
        const float    yv = __ldg(yr + c);
        unk = max(unk, kv);
        if (yv > 0.0f) pos |= m;
#pragma unroll
        for (int l = 0; l < NL; ++l)
            if (m & (1u << l)) lmaxk[l] = max(lmaxk[l], kv);
    }
#pragma unroll
    for (int s = 16; s > 0; s >>= 1) {
#pragma unroll
        for (int l = 0; l < NL; ++l)
            lmaxk[l] = max(lmaxk[l], __shfl_xor_sync(0xffffffffu, lmaxk[l], s));
        unk = max(unk, __shfl_xor_sync(0xffffffffu, unk, s));
        pos |= __shfl_xor_sync(0xffffffffu, pos, s);
    }
    const int warp = tid >> 5, lane = tid & 31;
    if (lane == 0) {
#pragma unroll
        for (int l = 0; l < NL; ++l) s_lmaxk[warp][l] = lmaxk[l];
        s_unk[warp] = unk;
        s_pb[warp]  = pos;
    }
    __syncthreads();

    if (tid == 0) {
#pragma unroll
        for (int w = 1; w < NTHR / 32; ++w) {
#pragma unroll
            for (int l = 0; l < NL; ++l) lmaxk[l] = max(lmaxk[l], s_lmaxk[w][l]);
            unk = max(unk, s_unk[w]);
            pos |= s_pb[w];
        }

        const float thres = fmaxf(sigmoidf_(k2f(key11)), 0.5f);   // ALPHA_OTHER

        unsigned ck = KNEG, ik = KNEG;
#pragma unroll
        for (int l = 0; l < NL; ++l) {
            if (pos & (1u << l)) ck = max(ck, lmaxk[l]);
            else                 ik = max(ik, lmaxk[l]);
        }

        float x1, x2, coef;
        if (pos) {                                   // any_correct
            x1   = sigmoidf_(k2f(ck));
            x2   = fmaxf(sigmoidf_(k2f(ik)), thres); // covers any_incorrect branch
            coef = 1.0f;
        } else {
            x1   = thres;
            x2   = sigmoidf_(k2f(unk));
            coef = 0.5f;                             // 1 - ALPHA
        }
        const float d    = x2 - x1 + 0.1f;           // ALPHA1
        const float rank = (d > 0.0f ? 2.0f : 1.0f) * sigmoidf_(10.0f * d);

        g_row_val[b] = coef * rank;
        __threadfence();
        const int t = atomicAdd(&g_done, 1);
        s_last = (t == BATCH - 1);
    }
    __syncthreads();

    // ---- last block: deterministic mean over g_row_val, reset state ----
    if (s_last) {
        float* s_red = (float*)s_hist;               // reuse smem
        float acc = 0.0f;
        for (int i = tid; i < BATCH; i += NTHR) acc += g_row_val[i];
        s_red[tid] = acc;
        __syncthreads();
        for (int off = NTHR / 2; off > 0; off >>= 1) {
            if (tid < off) s_red[tid] += s_red[tid + off];
            __syncthreads();
        }
        if (tid == 0) {
            out[0]     = s_red[0] * (1.0f / (float)BATCH);
            g_done     = 0;                          // reset for next replay
            g_wl_count = 0;
        }
    }
}

extern "C" void kernel_launch(void* const* d_in, const int* in_sizes, int n_in,
                              void* d_out, int out_size) {
    const float* x  = (const float*)d_in[0];
    const float* y  = (const float*)d_in[1];
    // d_in[2] = y_neg: never affects the result, never read.
    const void*  wl = d_in[3];

    build_wl_kernel<<<WLB, NTHR>>>(wl);
    row_kernel<<<BATCH, NTHR>>>(x, y, (float*)d_out);
}

// round 7
// speedup vs baseline: 2.9478x; 2.9478x over previous
#include <cuda_runtime.h>
#include <math.h>

#define BATCH 2048
#define NC    9605
#define NL    8
#define MAXWL 512
#define NTHR  256
#define WLB   32
#define CAP   256     // max candidates collected before deeper refine (exact fallback)

__device__ int           g_wl_count;   // 0-init; reset by row tail each launch
__device__ int           g_wl_idx[MAXWL];
__device__ unsigned char g_wl_mask[MAXWL];
__device__ float         g_row_val[BATCH];
__device__ int           g_done;       // 0-init; reset by row tail each launch

__device__ __forceinline__ float sigmoidf_(float v) {
    return 1.0f / (1.0f + expf(-v));   // v = -1e30 -> 0 (correct)
}
__device__ __forceinline__ unsigned f2k(unsigned u) {          // monotone float->uint
    return (u & 0x80000000u) ? ~u : (u | 0x80000000u);
}
__device__ __forceinline__ float k2f(unsigned k) {
    return (k & 0x80000000u) ? __uint_as_float(k ^ 0x80000000u)
                             : __uint_as_float(~k);
}

// ---------------------------------------------------------------------------
// Kernel 1: fused dtype-sniff + whitelist compaction (bool may arrive as
// f32/i32/u8). Each block rescans flags from L2 (77KB), then builds its stripe.
// ---------------------------------------------------------------------------
__global__ void __launch_bounds__(NTHR) build_wl_kernel(const void* __restrict__ wlraw) {
    __shared__ int fl[4];
    const int tid = threadIdx.x;
    if (tid < 4) fl[tid] = 0;
    __syncthreads();

    const int NQ = (NL * NC) / 4;
    const int*   ip = (const int*)wlraw;
    const float* fp = (const float*)wlraw;
    for (int i = tid; i < NQ; i += NTHR) {
        int v = ip[i];
        float f = fp[i];
        if (v != 0 && v != 1)          fl[0] = 1;
        if (!(f == 0.0f || f == 1.0f)) fl[2] = 1;
        if (f == 1.0f)                 fl[3] = 1;
    }
    __syncthreads();
    const int mode = (!fl[2] && fl[3]) ? 2 : (!fl[0] ? 1 : 0);  // 2=f32,1=i32,0=u8
    const unsigned char* up = (const unsigned char*)wlraw;

    for (int c = blockIdx.x * NTHR + tid; c < NC; c += WLB * NTHR) {
        unsigned m = 0;
#pragma unroll
        for (int l = 0; l < NL; ++l) {
            bool on;
            if      (mode == 2) on = (fp[l * NC + c] != 0.0f);
            else if (mode == 1) on = (ip[l * NC + c] != 0);
            else                on = (up[l * NC + c] != 0);
            if (on) m |= (1u << l);
        }
        if (m) {
            int p = atomicAdd(&g_wl_count, 1);
            g_wl_idx[p]  = c;
            g_wl_mask[p] = (unsigned char)m;
        }
    }
}

// ---------------------------------------------------------------------------
// pick8: suffix-select over 2048 bins (thread t owns bins [8t, 8t+8)).
// Finds bin holding the want-th largest, its in-bin rank, and its count.
// ---------------------------------------------------------------------------
__device__ __forceinline__ void pick8(const unsigned* __restrict__ hist,
                                      unsigned* __restrict__ wsum,
                                      unsigned* __restrict__ sb,
                                      unsigned* __restrict__ sw,
                                      unsigned* __restrict__ sc,
                                      unsigned want, int tid) {
    unsigned v[8];
    unsigned tot = 0;
#pragma unroll
    for (int i = 0; i < 8; ++i) { v[i] = hist[tid * 8 + i]; tot += v[i]; }
    unsigned incl = tot;
#pragma unroll
    for (int d = 1; d < 32; d <<= 1) {
        unsigned n = __shfl_down_sync(0xffffffffu, incl, d);
        if ((tid & 31) + d < 32) incl += n;
    }
    if ((tid & 31) == 0) wsum[tid >> 5] = incl;
    __syncthreads();
    unsigned above = incl - tot;
#pragma unroll
    for (int w = 0; w < NTHR / 32; ++w)
        if (w > (tid >> 5)) above += wsum[w];
    unsigned suf = above;
#pragma unroll
    for (int j = 7; j >= 0; --j) {
        unsigned nsuf = suf + v[j];
        if (suf < want && want <= nsuf) {
            *sb = (unsigned)(tid * 8 + j); *sw = want - suf; *sc = v[j];
        }
        suf = nsuf;
    }
    __syncthreads();
}

// pick1: suffix-select over <=256 bins, thread t owns bin t.
__device__ __forceinline__ void pick1(const unsigned* __restrict__ hist, int nbins,
                                      unsigned* __restrict__ wsum,
                                      unsigned* __restrict__ sb,
                                      unsigned* __restrict__ sw,
                                      unsigned* __restrict__ sc,
                                      unsigned want, int tid) {
    unsigned v = (tid < nbins) ? hist[tid] : 0u;
    unsigned incl = v;
#pragma unroll
    for (int d = 1; d < 32; d <<= 1) {
        unsigned n = __shfl_down_sync(0xffffffffu, incl, d);
        if ((tid & 31) + d < 32) incl += n;
    }
    if ((tid & 31) == 0) wsum[tid >> 5] = incl;
    __syncthreads();
    unsigned above = incl - v;
#pragma unroll
    for (int w = 0; w < NTHR / 32; ++w)
        if (w > (tid >> 5)) above += wsum[w];
    if (above < want && want <= above + v) { *sb = (unsigned)tid; *sw = want - above; *sc = v; }
    __syncthreads();
}

// ---------------------------------------------------------------------------
// Kernel 2: one block per row.
//  A) 8-wide register-batched DRAM stream + 2048-bin (11-bit) histogram
//  B) refine: collect <=CAP prefix-matching keys from L2, rank-select exactly
//     (generic 8-bit-chunk deepening for pathological tie counts)
//  C) whitelist maxes / pos bits / union max from L2; epilogue; last-block mean
// ---------------------------------------------------------------------------
__global__ void __launch_bounds__(NTHR, 8)
row_kernel(const float* __restrict__ x, const float* __restrict__ y,
           float* __restrict__ out) {
    __shared__ unsigned s_hist[2048];
    __shared__ unsigned s_wsum[NTHR / 32];
    __shared__ unsigned s_bin, s_want, s_cnt;
    __shared__ unsigned s_cand[CAP];
    __shared__ unsigned s_ncand, s_sel;
    __shared__ unsigned s_lmaxk[NTHR / 32][NL];
    __shared__ unsigned s_unk[NTHR / 32];
    __shared__ unsigned s_pb[NTHR / 32];
    __shared__ int      s_last;

    const int b   = blockIdx.x;
    const int tid = threadIdx.x;
    const float* xr = x + (size_t)b * NC;
    const float* yr = y + (size_t)b * NC;

#pragma unroll
    for (int i = 0; i < 8; ++i) s_hist[tid * 8 + i] = 0;
    __syncthreads();

    // ---- phase A: batched loads (MLP=8), then histogram top-11 key bits ----
    for (int base = 0; base < NC; base += NTHR * 8) {
        unsigned k[8];
        bool     v[8];
#pragma unroll
        for (int u = 0; u < 8; ++u) {
            const int c = base + u * NTHR + tid;
            v[u] = (c < NC);
            k[u] = v[u] ? f2k(__float_as_uint(__ldg(xr + c))) : 0u;
        }
#pragma unroll
        for (int u = 0; u < 8; ++u)
            if (v[u]) atomicAdd(&s_hist[k[u] >> 21], 1u);
    }
    __syncthreads();

    // ---- level 0: pick 11-bit prefix ----
    unsigned want = 11;
    pick8(s_hist, s_wsum, &s_bin, &s_want, &s_cnt, want, tid);
    unsigned prefix = s_bin;
    int      pbits  = 11;
    unsigned cnt    = s_cnt;
    want = s_want;
    __syncthreads();

    // ---- exact deepening for pathological tie counts (never on normal data) ----
    while (cnt > CAP && pbits < 32) {
        const int nb = (32 - pbits < 8) ? (32 - pbits) : 8;
        if (tid < (1 << nb)) s_hist[tid] = 0;
        __syncthreads();
        for (int c = tid; c < NC; c += NTHR) {
            const unsigned key = f2k(__float_as_uint(__ldg(xr + c)));
            if ((key >> (32 - pbits)) == prefix)
                atomicAdd(&s_hist[(key >> (32 - pbits - nb)) & ((1u << nb) - 1u)], 1u);
        }
        __syncthreads();
        pick1(s_hist, 1 << nb, s_wsum, &s_bin, &s_want, &s_cnt, want, tid);
        prefix = (prefix << nb) | s_bin;
        pbits += nb;
        cnt  = s_cnt;
        want = s_want;
        __syncthreads();
    }

    unsigned key11;
    if (pbits >= 32) {
        key11 = prefix;                          // all remaining bits tied
    } else {
        // ---- collect matching keys from L2 (row just streamed; resident) ----
        if (tid == 0) s_ncand = 0;
        __syncthreads();
        for (int base = 0; base < NC; base += NTHR * 8) {
            unsigned k[8];
            bool     v[8];
#pragma unroll
            for (int u = 0; u < 8; ++u) {
                const int c = base + u * NTHR + tid;
                v[u] = (c < NC);
                k[u] = v[u] ? f2k(__float_as_uint(__ldg(xr + c))) : 0u;
            }
#pragma unroll
            for (int u = 0; u < 8; ++u)
                if (v[u] && (k[u] >> (32 - pbits)) == prefix)
                    s_cand[atomicAdd(&s_ncand, 1u)] = k[u];
        }
        __syncthreads();
        const int n = (int)s_ncand;              // == cnt <= CAP
        if (tid < n) {
            const unsigned kk = s_cand[tid];
            unsigned gt = 0, ge = 0;
            for (int j = 0; j < n; ++j) {
                gt += (s_cand[j] > kk);
                ge += (s_cand[j] >= kk);
            }
            if (gt < want && want <= ge) s_sel = kk;   // unique value, any writer
        }
        __syncthreads();
        key11 = s_sel;
    }

    // ---- whitelist gather straight from L2/DRAM ----
    const unsigned KNEG = f2k(__float_as_uint(-1e30f));
    const int nwl = g_wl_count;
    unsigned lmaxk[NL];
#pragma unroll
    for (int l = 0; l < NL; ++l) lmaxk[l] = KNEG;
    unsigned unk = KNEG, pos = 0;

    for (int e = tid; e < nwl; e += NTHR) {
        const int      c  = g_wl_idx[e];
        const unsigned m  = g_wl_mask[e];
        const unsigned kv = f2k(__float_as_uint(__ldg(xr + c)));
        const float    yv = __ldg(yr + c);
        unk = max(unk, kv);
        if (yv > 0.0f) pos |= m;
#pragma unroll
        for (int l = 0; l < NL; ++l)
            if (m & (1u << l)) lmaxk[l] = max(lmaxk[l], kv);
    }
#pragma unroll
    for (int s = 16; s > 0; s >>= 1) {
#pragma unroll
        for (int l = 0; l < NL; ++l)
            lmaxk[l] = max(lmaxk[l], __shfl_xor_sync(0xffffffffu, lmaxk[l], s));
        unk = max(unk, __shfl_xor_sync(0xffffffffu, unk, s));
        pos |= __shfl_xor_sync(0xffffffffu, pos, s);
    }
    const int warp = tid >> 5, lane = tid & 31;
    if (lane == 0) {
#pragma unroll
        for (int l = 0; l < NL; ++l) s_lmaxk[warp][l] = lmaxk[l];
        s_unk[warp] = unk;
        s_pb[warp]  = pos;
    }
    __syncthreads();

    if (tid == 0) {
#pragma unroll
        for (int w = 1; w < NTHR / 32; ++w) {
#pragma unroll
            for (int l = 0; l < NL; ++l) lmaxk[l] = max(lmaxk[l], s_lmaxk[w][l]);
            unk = max(unk, s_unk[w]);
            pos |= s_pb[w];
        }

        const float thres = fmaxf(sigmoidf_(k2f(key11)), 0.5f);   // ALPHA_OTHER

        unsigned ck = KNEG, ik = KNEG;
#pragma unroll
        for (int l = 0; l < NL; ++l) {
            if (pos & (1u << l)) ck = max(ck, lmaxk[l]);
            else                 ik = max(ik, lmaxk[l]);
        }

        float x1, x2, coef;
        if (pos) {                                   // any_correct
            x1   = sigmoidf_(k2f(ck));
            x2   = fmaxf(sigmoidf_(k2f(ik)), thres); // covers any_incorrect branch
            coef = 1.0f;
        } else {
            x1   = thres;
            x2   = sigmoidf_(k2f(unk));
            coef = 0.5f;                             // 1 - ALPHA
        }
        const float d    = x2 - x1 + 0.1f;           // ALPHA1
        const float rank = (d > 0.0f ? 2.0f : 1.0f) * sigmoidf_(10.0f * d);

        g_row_val[b] = coef * rank;
        __threadfence();
        const int t = atomicAdd(&g_done, 1);
        s_last = (t == BATCH - 1);
    }
    __syncthreads();

    // ---- last block: deterministic mean, reset persistent state ----
    if (s_last) {
        float* s_red = (float*)s_hist;
        float acc = 0.0f;
        for (int i = tid; i < BATCH; i += NTHR) acc += g_row_val[i];
        s_red[tid] = acc;
        __syncthreads();
        for (int off = NTHR / 2; off > 0; off >>= 1) {
            if (tid < off) s_red[tid] += s_red[tid + off];
            __syncthreads();
        }
        if (tid == 0) {
            out[0]     = s_red[0] * (1.0f / (float)BATCH);
            g_done     = 0;
            g_wl_count = 0;
        }
    }
}

extern "C" void kernel_launch(void* const* d_in, const int* in_sizes, int n_in,
                              void* d_out, int out_size) {
    const float* x  = (const float*)d_in[0];
    const float* y  = (const float*)d_in[1];
    // d_in[2] = y_neg: never affects the result, never read.
    const void*  wl = d_in[3];

    build_wl_kernel<<<WLB, NTHR>>>(wl);
    row_kernel<<<BATCH, NTHR>>>(x, y, (float*)d_out);
}